// round 14
// baseline (speedup 1.0000x reference)
#include <cuda_runtime.h>
#include <cuda_fp16.h>
#include <cstdint>

#define B_   32
#define NA   512
#define NV   256
#define D_   384
#define BM   128
#define BN   256
#define BKE  64                     // fp16 elements per k-chunk (128 bytes/row)
#define NCH  (D_ / BKE)             // 6
#define NSTG 2

#define A_TILE   (BM * 128)         // 16384 B
#define B_TILE   (BN * 128)         // 32768 B
#define STAGE_B  (A_TILE + B_TILE)  // 49152 B
#define SMEM_BYTES (NSTG * STAGE_B) // 98304 B -> 2 CTAs/SM

#define NTHREADS 256

// fp16 scratch (device globals: allocation-free)
__device__ __align__(16) __half g_audio_h[B_ * NA * D_];    // 12.6 MB
__device__ __align__(16) __half g_visual_h[B_ * NV * D_];   //  6.3 MB

// ---------------- helpers ----------------
__device__ __forceinline__ uint32_t smem_u32(const void* p) {
    uint32_t a;
    asm("{ .reg .u64 t; cvta.to.shared.u64 t, %1; cvt.u32.u64 %0, t; }" : "=r"(a) : "l"(p));
    return a;
}
#define CP_ASYNC16(dst, src) \
    asm volatile("cp.async.cg.shared.global [%0], [%1], 16;" :: "r"(dst), "l"(src) : "memory")
#define CP_COMMIT()  asm volatile("cp.async.commit_group;" ::: "memory")
#define CP_WAIT(N)   asm volatile("cp.async.wait_group %0;" :: "n"(N) : "memory")

#define LDSM_X4(r, addr) \
    asm volatile("ldmatrix.sync.aligned.m8n8.x4.shared.b16 {%0,%1,%2,%3}, [%4];" \
                 : "=r"((r)[0]), "=r"((r)[1]), "=r"((r)[2]), "=r"((r)[3]) : "r"(addr))

// fp16-accumulate MMA: D,C are 2 packed-half2 regs
__device__ __forceinline__ void mma_f16(uint32_t* d, const uint32_t* a, const uint32_t* b) {
    asm volatile(
        "mma.sync.aligned.m16n8k16.row.col.f16.f16.f16.f16 "
        "{%0,%1}, {%2,%3,%4,%5}, {%6,%7}, {%0,%1};"
        : "+r"(d[0]), "+r"(d[1])
        : "r"(a[0]), "r"(a[1]), "r"(a[2]), "r"(a[3]), "r"(b[0]), "r"(b[1]));
}

__device__ __forceinline__ void lse_comb(float& m, float& s, int o) {
    float om = __shfl_xor_sync(0xffffffffu, m, o);
    float os = __shfl_xor_sync(0xffffffffu, s, o);
    float mn = fmaxf(m, om);
    s = s * __expf((m - mn) * 0.5f) + os * __expf((om - mn) * 0.5f);
    m = mn;
}

// ---------------- fp32 -> fp16 conversion ----------------
__global__ void cvt_f16_kernel(const float* __restrict__ audio,
                               const float* __restrict__ visual) {
    const int NAE = B_ * NA * D_;
    const int NVE = B_ * NV * D_;
    int stride = gridDim.x * blockDim.x;
    for (int t = blockIdx.x * blockDim.x + threadIdx.x; t < NAE / 4; t += stride) {
        float4 v = reinterpret_cast<const float4*>(audio)[t];
        __half2 p0 = __floats2half2_rn(v.x, v.y);
        __half2 p1 = __floats2half2_rn(v.z, v.w);
        reinterpret_cast<uint2*>(g_audio_h)[t] =
            make_uint2(*reinterpret_cast<uint32_t*>(&p0), *reinterpret_cast<uint32_t*>(&p1));
    }
    for (int t = blockIdx.x * blockDim.x + threadIdx.x; t < NVE / 4; t += stride) {
        float4 v = reinterpret_cast<const float4*>(visual)[t];
        __half2 p0 = __floats2half2_rn(v.x, v.y);
        __half2 p1 = __floats2half2_rn(v.z, v.w);
        reinterpret_cast<uint2*>(g_visual_h)[t] =
            make_uint2(*reinterpret_cast<uint32_t*>(&p0), *reinterpret_cast<uint32_t*>(&p1));
    }
}

// ---------------- main fused kernel ----------------
__global__ void __launch_bounds__(NTHREADS, 2)
mm_f16_lse_kernel(float* __restrict__ out) {
    extern __shared__ char smem[];
    const uint32_t sb = smem_u32(smem);
    const int tid   = threadIdx.x;
    const int warp  = tid >> 5;
    const int lane  = tid & 31;
    const int warpm = warp >> 2;        // 0..1 -> 64-row strip
    const int warpn = warp & 3;         // 0..3 -> 64-col quarter
    const int g     = lane >> 2;        // 0..7
    const int c     = lane & 3;         // 0..3

    const int mt_b = blockIdx.x;        // 0..3
    const int j    = blockIdx.y;        // visual batch
    const int i    = blockIdx.z;        // audio batch

    const __half* Ab = g_audio_h  + ((size_t)i * NA + (size_t)mt_b * BM) * D_;
    const __half* Vb = g_visual_h + (size_t)j * NV * D_;

    uint32_t acc[4][8][2];              // packed half2: [mt][nt][row-half]
    #pragma unroll
    for (int mt = 0; mt < 4; mt++)
        #pragma unroll
        for (int nt = 0; nt < 8; nt++) { acc[mt][nt][0] = 0u; acc[mt][nt][1] = 0u; }

    // ---- stage loader: SW128-swizzled smem, cp.async 16B ----
    auto load_stage = [&](int s, int kc) {
        const uint32_t a_off = s * STAGE_B;
        const uint32_t b_off = a_off + A_TILE;
        const int kb = kc * BKE;
        #pragma unroll
        for (int e = 0; e < 4; e++) {             // A: 128 rows x 8 x 16B = 1024
            int idx = e * NTHREADS + tid;
            int row = idx >> 3, gg = idx & 7;
            uint32_t loc = row * 128 + ((gg * 16) ^ ((row & 7) << 4));
            CP_ASYNC16(sb + a_off + loc, Ab + (size_t)row * D_ + kb + gg * 8);
        }
        #pragma unroll
        for (int e = 0; e < 8; e++) {             // B: 256 rows x 8 x 16B = 2048
            int idx = e * NTHREADS + tid;
            int row = idx >> 3, gg = idx & 7;
            uint32_t loc = row * 128 + ((gg * 16) ^ ((row & 7) << 4));
            CP_ASYNC16(sb + b_off + loc, Vb + (size_t)row * D_ + kb + gg * 8);
        }
        CP_COMMIT();
    };

    // ---- per-lane ldmatrix address components ----
    const uint32_t a_row  = (uint32_t)(warpm * 64 + (lane & 15));
    const uint32_t a_cxtr = ((lane >> 4) & 1) * 16;
    const uint32_t b_row  = (uint32_t)(warpn * 64 + ((lane & 7) | ((lane & 16) >> 1)));
    const uint32_t b_cxtr = ((lane >> 3) & 1) * 16;
    const uint32_t swx    = (uint32_t)((lane & 7) << 4);

    auto compute = [&](int s) {
        const uint32_t a_base = sb + s * STAGE_B + a_row * 128;
        const uint32_t b_base = sb + s * STAGE_B + A_TILE + b_row * 128;
        #pragma unroll
        for (int ks = 0; ks < 4; ks++) {          // 4 x k16 per 64-wide chunk
            const uint32_t acol = (uint32_t)(ks * 32 + a_cxtr) ^ swx;
            const uint32_t bcol = (uint32_t)(ks * 32 + b_cxtr) ^ swx;
            uint32_t af[4][4], bf[4][4];
            #pragma unroll
            for (int mt = 0; mt < 4; mt++)
                LDSM_X4(af[mt], a_base + mt * (16 * 128) + acol);
            #pragma unroll
            for (int p = 0; p < 4; p++)
                LDSM_X4(bf[p], b_base + p * (16 * 128) + bcol);
            #pragma unroll
            for (int mt = 0; mt < 4; mt++)
                #pragma unroll
                for (int p = 0; p < 4; p++) {
                    mma_f16(acc[mt][2 * p],     af[mt], &bf[p][0]);
                    mma_f16(acc[mt][2 * p + 1], af[mt], &bf[p][2]);
                }
        }
    };

    // ---- 2-stage pipeline, ONE barrier per chunk ----
    // barrier at iter kc proves: chunk kc visible (post CP_WAIT) AND
    // compute(kc-1) finished CTA-wide -> its stage is free to refill.
    load_stage(0, 0);
    load_stage(1, 1);

    CP_WAIT(1);  __syncthreads();                  compute(0);
    CP_WAIT(0);  __syncthreads();  load_stage(0, 2); compute(1);
    CP_WAIT(0);  __syncthreads();  load_stage(1, 3); compute(0);
    CP_WAIT(0);  __syncthreads();  load_stage(0, 4); compute(1);
    CP_WAIT(0);  __syncthreads();  load_stage(1, 5); compute(0);
    CP_WAIT(0);  __syncthreads();                  compute(1);

    // ---- epilogue: tau*logsumexp over 256 cols, mean over rows ----
    // pmax/psum live in stage-0 region: free (last compute used stage 1,
    // and the final barrier above ordered all stage-0 readers).
    float* pmax = reinterpret_cast<float*>(smem);          // [128][4]
    float* psum = pmax + 512;                              // [128][4]
    float* wsum = pmax + 1024;                             // [4]

    #pragma unroll
    for (int mt = 0; mt < 4; mt++) {
        int r0 = warpm * 64 + mt * 16 + g;
        float v0[16], v1[16];
        #pragma unroll
        for (int nt = 0; nt < 8; nt++) {
            float2 x0 = __half22float2(*reinterpret_cast<__half2*>(&acc[mt][nt][0]));
            float2 x1 = __half22float2(*reinterpret_cast<__half2*>(&acc[mt][nt][1]));
            v0[2 * nt] = x0.x; v0[2 * nt + 1] = x0.y;
            v1[2 * nt] = x1.x; v1[2 * nt + 1] = x1.y;
        }
        float m0 = v0[0], m1 = v1[0];
        #pragma unroll
        for (int e = 1; e < 16; e++) { m0 = fmaxf(m0, v0[e]); m1 = fmaxf(m1, v1[e]); }
        float s0 = 0.f, s1 = 0.f;
        #pragma unroll
        for (int e = 0; e < 16; e++) {
            s0 += __expf((v0[e] - m0) * 0.5f);
            s1 += __expf((v1[e] - m1) * 0.5f);
        }
        lse_comb(m0, s0, 1); lse_comb(m0, s0, 2);
        lse_comb(m1, s1, 1); lse_comb(m1, s1, 2);
        if (c == 0) {
            pmax[(r0)     * 4 + warpn] = m0;  psum[(r0)     * 4 + warpn] = s0;
            pmax[(r0 + 8) * 4 + warpn] = m1;  psum[(r0 + 8) * 4 + warpn] = s1;
        }
    }
    __syncthreads();

    if (tid < 128) {
        float m = pmax[tid * 4];
        #pragma unroll
        for (int w = 1; w < 4; w++) m = fmaxf(m, pmax[tid * 4 + w]);
        float s = 0.f;
        #pragma unroll
        for (int w = 0; w < 4; w++) s += psum[tid * 4 + w] * __expf((pmax[tid * 4 + w] - m) * 0.5f);
        float lse = m + 2.0f * __logf(s);
        #pragma unroll
        for (int o = 16; o > 0; o >>= 1) lse += __shfl_xor_sync(0xffffffffu, lse, o);
        if (lane == 0) wsum[warp] = lse;
    }
    __syncthreads();
    if (tid == 0) {
        float t = wsum[0] + wsum[1] + wsum[2] + wsum[3];
        atomicAdd(&out[i * B_ + j], t * (1.0f / NA));
    }
}

// ---------------- launch ----------------
extern "C" void kernel_launch(void* const* d_in, const int* in_sizes, int n_in,
                              void* d_out, int out_size) {
    const float* audio  = (const float*)d_in[0];   // (32, 512, 384) fp32
    const float* visual = (const float*)d_in[1];   // (32, 256, 384) fp32
    float* out = (float*)d_out;                    // (32, 32) fp32

    cudaFuncSetAttribute(mm_f16_lse_kernel,
                         cudaFuncAttributeMaxDynamicSharedMemorySize, SMEM_BYTES);

    cudaMemsetAsync(out, 0, (size_t)out_size * sizeof(float));
    cvt_f16_kernel<<<1184, 256>>>(audio, visual);

    dim3 grid(NA / BM, B_, B_);   // (4, 32, 32)
    mm_f16_lse_kernel<<<grid, NTHREADS, SMEM_BYTES>>>(out);
}

// round 15
// speedup vs baseline: 1.0066x; 1.0066x over previous
#include <cuda_runtime.h>
#include <cuda_fp16.h>
#include <cstdint>

#define B_   32
#define NA   512
#define NV   256
#define D_   384
#define BM   128
#define BN   256
#define BKE  64                     // fp16 elements per k-chunk (128 bytes/row)
#define NCH  (D_ / BKE)             // 6
#define NSTG 2

#define A_TILE   (BM * 128)         // 16384 B
#define B_TILE   (BN * 128)         // 32768 B
#define STAGE_B  (A_TILE + B_TILE)  // 49152 B
#define SMEM_BYTES (NSTG * STAGE_B) // 98304 B -> 2 CTAs/SM

#define NTHREADS 256

// fp16 scratch (device globals: allocation-free)
__device__ __align__(16) __half g_audio_h[B_ * NA * D_];    // 12.6 MB
__device__ __align__(16) __half g_visual_h[B_ * NV * D_];   //  6.3 MB

// ---------------- helpers ----------------
__device__ __forceinline__ uint32_t smem_u32(const void* p) {
    uint32_t a;
    asm("{ .reg .u64 t; cvta.to.shared.u64 t, %1; cvt.u32.u64 %0, t; }" : "=r"(a) : "l"(p));
    return a;
}
#define CP_ASYNC16(dst, src) \
    asm volatile("cp.async.cg.shared.global [%0], [%1], 16;" :: "r"(dst), "l"(src) : "memory")
#define CP_COMMIT()  asm volatile("cp.async.commit_group;" ::: "memory")
#define CP_WAIT(N)   asm volatile("cp.async.wait_group %0;" :: "n"(N) : "memory")

#define LDSM_X4(r, addr) \
    asm volatile("ldmatrix.sync.aligned.m8n8.x4.shared.b16 {%0,%1,%2,%3}, [%4];" \
                 : "=r"((r)[0]), "=r"((r)[1]), "=r"((r)[2]), "=r"((r)[3]) : "r"(addr))

// fp16-accumulate MMA: D,C are 2 packed-half2 regs
__device__ __forceinline__ void mma_f16(uint32_t* d, const uint32_t* a, const uint32_t* b) {
    asm volatile(
        "mma.sync.aligned.m16n8k16.row.col.f16.f16.f16.f16 "
        "{%0,%1}, {%2,%3,%4,%5}, {%6,%7}, {%0,%1};"
        : "+r"(d[0]), "+r"(d[1])
        : "r"(a[0]), "r"(a[1]), "r"(a[2]), "r"(a[3]), "r"(b[0]), "r"(b[1]));
}

__device__ __forceinline__ void lse_comb(float& m, float& s, int o) {
    float om = __shfl_xor_sync(0xffffffffu, m, o);
    float os = __shfl_xor_sync(0xffffffffu, s, o);
    float mn = fmaxf(m, om);
    s = s * __expf((m - mn) * 0.5f) + os * __expf((om - mn) * 0.5f);
    m = mn;
}

// ---------------- fp32 -> fp16 conversion ----------------
__global__ void cvt_f16_kernel(const float* __restrict__ audio,
                               const float* __restrict__ visual) {
    const int NAE = B_ * NA * D_;
    const int NVE = B_ * NV * D_;
    int stride = gridDim.x * blockDim.x;
    for (int t = blockIdx.x * blockDim.x + threadIdx.x; t < NAE / 4; t += stride) {
        float4 v = reinterpret_cast<const float4*>(audio)[t];
        __half2 p0 = __floats2half2_rn(v.x, v.y);
        __half2 p1 = __floats2half2_rn(v.z, v.w);
        reinterpret_cast<uint2*>(g_audio_h)[t] =
            make_uint2(*reinterpret_cast<uint32_t*>(&p0), *reinterpret_cast<uint32_t*>(&p1));
    }
    for (int t = blockIdx.x * blockDim.x + threadIdx.x; t < NVE / 4; t += stride) {
        float4 v = reinterpret_cast<const float4*>(visual)[t];
        __half2 p0 = __floats2half2_rn(v.x, v.y);
        __half2 p1 = __floats2half2_rn(v.z, v.w);
        reinterpret_cast<uint2*>(g_visual_h)[t] =
            make_uint2(*reinterpret_cast<uint32_t*>(&p0), *reinterpret_cast<uint32_t*>(&p1));
    }
}

// ---------------- main fused kernel ----------------
__global__ void __launch_bounds__(NTHREADS, 2)
mm_f16_lse_kernel(float* __restrict__ out) {
    extern __shared__ char smem[];
    const uint32_t sb = smem_u32(smem);
    const int tid   = threadIdx.x;
    const int warp  = tid >> 5;
    const int lane  = tid & 31;
    const int warpm = warp >> 2;        // 0..1 -> 64-row strip
    const int warpn = warp & 3;         // 0..3 -> 64-col quarter
    const int g     = lane >> 2;        // 0..7
    const int c     = lane & 3;         // 0..3

    const int mt_b = blockIdx.x;        // 0..3
    const int j    = blockIdx.y;        // visual batch
    const int i    = blockIdx.z;        // audio batch

    const __half* Ab = g_audio_h  + ((size_t)i * NA + (size_t)mt_b * BM) * D_;
    const __half* Vb = g_visual_h + (size_t)j * NV * D_;

    uint32_t acc[4][8][2];              // packed half2: [mt][nt][row-half]
    #pragma unroll
    for (int mt = 0; mt < 4; mt++)
        #pragma unroll
        for (int nt = 0; nt < 8; nt++) { acc[mt][nt][0] = 0u; acc[mt][nt][1] = 0u; }

    // ---- stage loader: SW128-swizzled smem, cp.async 16B ----
    auto load_stage = [&](int s, int kc) {
        const uint32_t a_off = s * STAGE_B;
        const uint32_t b_off = a_off + A_TILE;
        const int kb = kc * BKE;
        #pragma unroll
        for (int e = 0; e < 4; e++) {             // A: 128 rows x 8 x 16B = 1024
            int idx = e * NTHREADS + tid;
            int row = idx >> 3, gg = idx & 7;
            uint32_t loc = row * 128 + ((gg * 16) ^ ((row & 7) << 4));
            CP_ASYNC16(sb + a_off + loc, Ab + (size_t)row * D_ + kb + gg * 8);
        }
        #pragma unroll
        for (int e = 0; e < 8; e++) {             // B: 256 rows x 8 x 16B = 2048
            int idx = e * NTHREADS + tid;
            int row = idx >> 3, gg = idx & 7;
            uint32_t loc = row * 128 + ((gg * 16) ^ ((row & 7) << 4));
            CP_ASYNC16(sb + b_off + loc, Vb + (size_t)row * D_ + kb + gg * 8);
        }
        CP_COMMIT();
    };

    // ---- per-lane ldmatrix address components ----
    const uint32_t a_row  = (uint32_t)(warpm * 64 + (lane & 15));
    const uint32_t a_cxtr = ((lane >> 4) & 1) * 16;
    const uint32_t b_row  = (uint32_t)(warpn * 64 + ((lane & 7) | ((lane & 16) >> 1)));
    const uint32_t b_cxtr = ((lane >> 3) & 1) * 16;
    const uint32_t swx    = (uint32_t)((lane & 7) << 4);

    // ---- compute one chunk with intra-chunk B-fragment double buffering ----
    auto compute = [&](int s) {
        const uint32_t a_base = sb + s * STAGE_B + a_row * 128;
        const uint32_t b_base = sb + s * STAGE_B + A_TILE + b_row * 128;
        uint32_t bf[2][4][4];
        // preload B fragments for ks = 0
        {
            const uint32_t bcol0 = (uint32_t)(b_cxtr) ^ swx;
            #pragma unroll
            for (int p = 0; p < 4; p++)
                LDSM_X4(bf[0][p], b_base + p * (16 * 128) + bcol0);
        }
        #pragma unroll
        for (int ks = 0; ks < 4; ks++) {
            const uint32_t acol = (uint32_t)(ks * 32 + a_cxtr) ^ swx;
            uint32_t af[4][4];
            #pragma unroll
            for (int mt = 0; mt < 4; mt++)
                LDSM_X4(af[mt], a_base + mt * (16 * 128) + acol);
            if (ks < 3) {   // prefetch next step's B fragments under this step's MMAs
                const uint32_t bcoln = (uint32_t)((ks + 1) * 32 + b_cxtr) ^ swx;
                #pragma unroll
                for (int p = 0; p < 4; p++)
                    LDSM_X4(bf[(ks + 1) & 1][p], b_base + p * (16 * 128) + bcoln);
            }
            #pragma unroll
            for (int mt = 0; mt < 4; mt++)
                #pragma unroll
                for (int p = 0; p < 4; p++) {
                    mma_f16(acc[mt][2 * p],     af[mt], &bf[ks & 1][p][0]);
                    mma_f16(acc[mt][2 * p + 1], af[mt], &bf[ks & 1][p][2]);
                }
        }
    };

    // ---- 2-stage pipeline, ONE barrier per chunk ----
    load_stage(0, 0);
    load_stage(1, 1);

    CP_WAIT(1);  __syncthreads();                    compute(0);
    CP_WAIT(0);  __syncthreads();  load_stage(0, 2); compute(1);
    CP_WAIT(0);  __syncthreads();  load_stage(1, 3); compute(0);
    CP_WAIT(0);  __syncthreads();  load_stage(0, 4); compute(1);
    CP_WAIT(0);  __syncthreads();  load_stage(1, 5); compute(0);
    CP_WAIT(0);  __syncthreads();                    compute(1);

    // ---- epilogue: tau*logsumexp over 256 cols, mean over rows ----
    float* pmax = reinterpret_cast<float*>(smem);          // [128][4]
    float* psum = pmax + 512;                              // [128][4]
    float* wsum = pmax + 1024;                             // [4]

    #pragma unroll
    for (int mt = 0; mt < 4; mt++) {
        int r0 = warpm * 64 + mt * 16 + g;
        float v0[16], v1[16];
        #pragma unroll
        for (int nt = 0; nt < 8; nt++) {
            float2 x0 = __half22float2(*reinterpret_cast<__half2*>(&acc[mt][nt][0]));
            float2 x1 = __half22float2(*reinterpret_cast<__half2*>(&acc[mt][nt][1]));
            v0[2 * nt] = x0.x; v0[2 * nt + 1] = x0.y;
            v1[2 * nt] = x1.x; v1[2 * nt + 1] = x1.y;
        }
        float m0 = v0[0], m1 = v1[0];
        #pragma unroll
        for (int e = 1; e < 16; e++) { m0 = fmaxf(m0, v0[e]); m1 = fmaxf(m1, v1[e]); }
        float s0 = 0.f, s1 = 0.f;
        #pragma unroll
        for (int e = 0; e < 16; e++) {
            s0 += __expf((v0[e] - m0) * 0.5f);
            s1 += __expf((v1[e] - m1) * 0.5f);
        }
        lse_comb(m0, s0, 1); lse_comb(m0, s0, 2);
        lse_comb(m1, s1, 1); lse_comb(m1, s1, 2);
        if (c == 0) {
            pmax[(r0)     * 4 + warpn] = m0;  psum[(r0)     * 4 + warpn] = s0;
            pmax[(r0 + 8) * 4 + warpn] = m1;  psum[(r0 + 8) * 4 + warpn] = s1;
        }
    }
    __syncthreads();

    if (tid < 128) {
        float m = pmax[tid * 4];
        #pragma unroll
        for (int w = 1; w < 4; w++) m = fmaxf(m, pmax[tid * 4 + w]);
        float s = 0.f;
        #pragma unroll
        for (int w = 0; w < 4; w++) s += psum[tid * 4 + w] * __expf((pmax[tid * 4 + w] - m) * 0.5f);
        float lse = m + 2.0f * __logf(s);
        #pragma unroll
        for (int o = 16; o > 0; o >>= 1) lse += __shfl_xor_sync(0xffffffffu, lse, o);
        if (lane == 0) wsum[warp] = lse;
    }
    __syncthreads();
    if (tid == 0) {
        float t = wsum[0] + wsum[1] + wsum[2] + wsum[3];
        atomicAdd(&out[i * B_ + j], t * (1.0f / NA));
    }
}

// ---------------- launch ----------------
extern "C" void kernel_launch(void* const* d_in, const int* in_sizes, int n_in,
                              void* d_out, int out_size) {
    const float* audio  = (const float*)d_in[0];   // (32, 512, 384) fp32
    const float* visual = (const float*)d_in[1];   // (32, 256, 384) fp32
    float* out = (float*)d_out;                    // (32, 32) fp32

    cudaFuncSetAttribute(mm_f16_lse_kernel,
                         cudaFuncAttributeMaxDynamicSharedMemorySize, SMEM_BYTES);

    cudaMemsetAsync(out, 0, (size_t)out_size * sizeof(float));
    cvt_f16_kernel<<<1184, 256>>>(audio, visual);

    dim3 grid(NA / BM, B_, B_);   // (4, 32, 32)
    mm_f16_lse_kernel<<<grid, NTHREADS, SMEM_BYTES>>>(out);
}

// round 16
// speedup vs baseline: 1.0862x; 1.0791x over previous
#include <cuda_runtime.h>
#include <cuda_fp16.h>
#include <cuda.h>
#include <cstdint>

#define B_   32
#define NA   512
#define NV   256
#define D_   384
#define BM   128
#define BN   256
#define BKE  64                     // fp16 elements per k-chunk (128 bytes/row)
#define NCH  (D_ / BKE)             // 6

#define A_TILE   (BM * 128)         // 16384 B
#define B_TILE   (BN * 128)         // 32768 B
#define STAGE_B  (A_TILE + B_TILE)  // 49152 B
#define RING_B   (2 * STAGE_B)      // 98304 B
#define SMEM_BYTES (RING_B + 64)    // + mbarriers -> 2 CTAs/SM

#define NTHREADS 256

// fp16 scratch (device globals: allocation-free)
__device__ __align__(16) __half g_audio_h[B_ * NA * D_];    // 12.6 MB
__device__ __align__(16) __half g_visual_h[B_ * NV * D_];   //  6.3 MB

// ---------------- helpers ----------------
__device__ __forceinline__ uint32_t smem_u32(const void* p) {
    uint32_t a;
    asm("{ .reg .u64 t; cvta.to.shared.u64 t, %1; cvt.u32.u64 %0, t; }" : "=r"(a) : "l"(p));
    return a;
}
#define MBAR_INIT(addr, cnt) \
    asm volatile("mbarrier.init.shared.b64 [%0], %1;" :: "r"(addr), "r"(cnt) : "memory")
#define MBAR_EXPECT(addr, bytes) \
    asm volatile("mbarrier.arrive.expect_tx.shared.b64 _, [%0], %1;" :: "r"(addr), "r"(bytes) : "memory")

__device__ __forceinline__ void mbar_wait(uint32_t mbar, uint32_t parity) {
    uint32_t done;
    asm volatile(
        "{ .reg .pred p; mbarrier.try_wait.parity.acquire.cta.shared::cta.b64 p, [%1], %2; selp.b32 %0, 1, 0, p; }"
        : "=r"(done) : "r"(mbar), "r"(parity) : "memory");
    while (!done) {
        asm volatile(
            "{ .reg .pred p; mbarrier.try_wait.parity.acquire.cta.shared::cta.b64 p, [%1], %2, 0x989680; selp.b32 %0, 1, 0, p; }"
            : "=r"(done) : "r"(mbar), "r"(parity) : "memory");
    }
}

__device__ __forceinline__ void tma2d(uint32_t dst, const CUtensorMap* map,
                                      int cx, int cy, uint32_t mbar) {
    asm volatile(
        "cp.async.bulk.tensor.2d.shared::cta.global.tile.mbarrier::complete_tx::bytes "
        "[%0], [%1, {%2, %3}], [%4];"
        :: "r"(dst), "l"(map), "r"(cx), "r"(cy), "r"(mbar) : "memory");
}

#define LDSM_X4(r, addr) \
    asm volatile("ldmatrix.sync.aligned.m8n8.x4.shared.b16 {%0,%1,%2,%3}, [%4];" \
                 : "=r"((r)[0]), "=r"((r)[1]), "=r"((r)[2]), "=r"((r)[3]) : "r"(addr))

// fp16-accumulate MMA: D,C are 2 packed-half2 regs
__device__ __forceinline__ void mma_f16(uint32_t* d, const uint32_t* a, const uint32_t* b) {
    asm volatile(
        "mma.sync.aligned.m16n8k16.row.col.f16.f16.f16.f16 "
        "{%0,%1}, {%2,%3,%4,%5}, {%6,%7}, {%0,%1};"
        : "+r"(d[0]), "+r"(d[1])
        : "r"(a[0]), "r"(a[1]), "r"(a[2]), "r"(a[3]), "r"(b[0]), "r"(b[1]));
}

__device__ __forceinline__ void lse_comb(float& m, float& s, int o) {
    float om = __shfl_xor_sync(0xffffffffu, m, o);
    float os = __shfl_xor_sync(0xffffffffu, s, o);
    float mn = fmaxf(m, om);
    s = s * __expf((m - mn) * 0.5f) + os * __expf((om - mn) * 0.5f);
    m = mn;
}

// ---------------- fp32 -> fp16 conversion ----------------
__global__ void cvt_f16_kernel(const float* __restrict__ audio,
                               const float* __restrict__ visual) {
    const int NAE = B_ * NA * D_;
    const int NVE = B_ * NV * D_;
    int stride = gridDim.x * blockDim.x;
    for (int t = blockIdx.x * blockDim.x + threadIdx.x; t < NAE / 4; t += stride) {
        float4 v = reinterpret_cast<const float4*>(audio)[t];
        __half2 p0 = __floats2half2_rn(v.x, v.y);
        __half2 p1 = __floats2half2_rn(v.z, v.w);
        reinterpret_cast<uint2*>(g_audio_h)[t] =
            make_uint2(*reinterpret_cast<uint32_t*>(&p0), *reinterpret_cast<uint32_t*>(&p1));
    }
    for (int t = blockIdx.x * blockDim.x + threadIdx.x; t < NVE / 4; t += stride) {
        float4 v = reinterpret_cast<const float4*>(visual)[t];
        __half2 p0 = __floats2half2_rn(v.x, v.y);
        __half2 p1 = __floats2half2_rn(v.z, v.w);
        reinterpret_cast<uint2*>(g_visual_h)[t] =
            make_uint2(*reinterpret_cast<uint32_t*>(&p0), *reinterpret_cast<uint32_t*>(&p1));
    }
}

// ---------------- main fused kernel ----------------
__global__ void __launch_bounds__(NTHREADS, 2)
mm_f16_lse_kernel(float* __restrict__ out,
                  const __grid_constant__ CUtensorMap mapA,
                  const __grid_constant__ CUtensorMap mapV) {
    extern __shared__ char smem[];
    const uint32_t sb = smem_u32(smem);
    const int tid   = threadIdx.x;
    const int warp  = tid >> 5;
    const int lane  = tid & 31;
    const int warpm = warp >> 2;        // 0..1 -> 64-row strip
    const int warpn = warp & 3;         // 0..3 -> 64-col quarter
    const int g     = lane >> 2;        // 0..7
    const int c     = lane & 3;         // 0..3

    const int mt_b = blockIdx.x;        // 0..3
    const int j    = blockIdx.y;        // visual batch
    const int i    = blockIdx.z;        // audio batch

    const int a_cy = i * NA + mt_b * BM;   // A row coord
    const int v_cy = j * NV;               // V row coord

    const uint32_t bar0 = sb + RING_B;
    const uint32_t bar1 = sb + RING_B + 8;

    uint32_t acc[4][8][2];              // packed half2: [mt][nt][row-half]
    #pragma unroll
    for (int mt = 0; mt < 4; mt++)
        #pragma unroll
        for (int nt = 0; nt < 8; nt++) { acc[mt][nt][0] = 0u; acc[mt][nt][1] = 0u; }

    if (tid == 0) {
        MBAR_INIT(bar0, 1);
        MBAR_INIT(bar1, 1);
    }
    __syncthreads();

    // issue TMA pair (A box [64,128], V box [64,256]) for chunk kc into stage s
    auto tma_stage = [&](int s, int kc, uint32_t bar) {
        MBAR_EXPECT(bar, STAGE_B);
        tma2d(sb + s * STAGE_B,          &mapA, kc * BKE, a_cy, bar);
        tma2d(sb + s * STAGE_B + A_TILE, &mapV, kc * BKE, v_cy, bar);
    };

    // ---- per-lane ldmatrix address components ----
    const uint32_t a_row  = (uint32_t)(warpm * 64 + (lane & 15));
    const uint32_t a_cxtr = ((lane >> 4) & 1) * 16;
    const uint32_t b_row  = (uint32_t)(warpn * 64 + ((lane & 7) | ((lane & 16) >> 1)));
    const uint32_t b_cxtr = ((lane >> 3) & 1) * 16;
    const uint32_t swx    = (uint32_t)((lane & 7) << 4);

    // ---- compute one chunk with intra-chunk B-fragment double buffering ----
    auto compute = [&](int s) {
        const uint32_t a_base = sb + s * STAGE_B + a_row * 128;
        const uint32_t b_base = sb + s * STAGE_B + A_TILE + b_row * 128;
        uint32_t bf[2][4][4];
        {
            const uint32_t bcol0 = (uint32_t)(b_cxtr) ^ swx;
            #pragma unroll
            for (int p = 0; p < 4; p++)
                LDSM_X4(bf[0][p], b_base + p * (16 * 128) + bcol0);
        }
        #pragma unroll
        for (int ks = 0; ks < 4; ks++) {
            const uint32_t acol = (uint32_t)(ks * 32 + a_cxtr) ^ swx;
            uint32_t af[4][4];
            #pragma unroll
            for (int mt = 0; mt < 4; mt++)
                LDSM_X4(af[mt], a_base + mt * (16 * 128) + acol);
            if (ks < 3) {
                const uint32_t bcoln = (uint32_t)((ks + 1) * 32 + b_cxtr) ^ swx;
                #pragma unroll
                for (int p = 0; p < 4; p++)
                    LDSM_X4(bf[(ks + 1) & 1][p], b_base + p * (16 * 128) + bcoln);
            }
            #pragma unroll
            for (int mt = 0; mt < 4; mt++)
                #pragma unroll
                for (int p = 0; p < 4; p++) {
                    mma_f16(acc[mt][2 * p],     af[mt], &bf[ks & 1][p][0]);
                    mma_f16(acc[mt][2 * p + 1], af[mt], &bf[ks & 1][p][2]);
                }
        }
    };

    // ---- 2-stage TMA pipeline, ONE barrier per chunk ----
    if (tid == 0) {
        tma_stage(0, 0, bar0);
        tma_stage(1, 1, bar1);
    }

    mbar_wait(bar0, 0); compute(0); __syncthreads();
    if (tid == 0) tma_stage(0, 2, bar0);
    mbar_wait(bar1, 0); compute(1); __syncthreads();
    if (tid == 0) tma_stage(1, 3, bar1);
    mbar_wait(bar0, 1); compute(0); __syncthreads();
    if (tid == 0) tma_stage(0, 4, bar0);
    mbar_wait(bar1, 1); compute(1); __syncthreads();
    if (tid == 0) tma_stage(1, 5, bar1);
    mbar_wait(bar0, 0); compute(0); __syncthreads();
    mbar_wait(bar1, 0); compute(1);

    // ---- epilogue: tau*logsumexp over 256 cols, mean over rows ----
    // pmax/psum live in stage-0 region (all stage-0 readers ordered by the
    // __syncthreads after the last compute(0); no TMA is pending on stage 0).
    float* pmax = reinterpret_cast<float*>(smem);          // [128][4]
    float* psum = pmax + 512;                              // [128][4]
    float* wsum = pmax + 1024;                             // [4]

    #pragma unroll
    for (int mt = 0; mt < 4; mt++) {
        int r0 = warpm * 64 + mt * 16 + g;
        float v0[16], v1[16];
        #pragma unroll
        for (int nt = 0; nt < 8; nt++) {
            float2 x0 = __half22float2(*reinterpret_cast<__half2*>(&acc[mt][nt][0]));
            float2 x1 = __half22float2(*reinterpret_cast<__half2*>(&acc[mt][nt][1]));
            v0[2 * nt] = x0.x; v0[2 * nt + 1] = x0.y;
            v1[2 * nt] = x1.x; v1[2 * nt + 1] = x1.y;
        }
        float m0 = v0[0], m1 = v1[0];
        #pragma unroll
        for (int e = 1; e < 16; e++) { m0 = fmaxf(m0, v0[e]); m1 = fmaxf(m1, v1[e]); }
        float s0 = 0.f, s1 = 0.f;
        #pragma unroll
        for (int e = 0; e < 16; e++) {
            s0 += __expf((v0[e] - m0) * 0.5f);
            s1 += __expf((v1[e] - m1) * 0.5f);
        }
        lse_comb(m0, s0, 1); lse_comb(m0, s0, 2);
        lse_comb(m1, s1, 1); lse_comb(m1, s1, 2);
        if (c == 0) {
            pmax[(r0)     * 4 + warpn] = m0;  psum[(r0)     * 4 + warpn] = s0;
            pmax[(r0 + 8) * 4 + warpn] = m1;  psum[(r0 + 8) * 4 + warpn] = s1;
        }
    }
    __syncthreads();

    if (tid < 128) {
        float m = pmax[tid * 4];
        #pragma unroll
        for (int w = 1; w < 4; w++) m = fmaxf(m, pmax[tid * 4 + w]);
        float s = 0.f;
        #pragma unroll
        for (int w = 0; w < 4; w++) s += psum[tid * 4 + w] * __expf((pmax[tid * 4 + w] - m) * 0.5f);
        float lse = m + 2.0f * __logf(s);
        #pragma unroll
        for (int o = 16; o > 0; o >>= 1) lse += __shfl_xor_sync(0xffffffffu, lse, o);
        if (lane == 0) wsum[warp] = lse;
    }
    __syncthreads();
    if (tid == 0) {
        float t = wsum[0] + wsum[1] + wsum[2] + wsum[3];
        atomicAdd(&out[i * B_ + j], t * (1.0f / NA));
    }
}

// ---------------- launch ----------------
typedef CUresult (*PFN_encodeTM)(
    CUtensorMap*, CUtensorMapDataType, cuuint32_t, void*,
    const cuuint64_t*, const cuuint64_t*, const cuuint32_t*, const cuuint32_t*,
    CUtensorMapInterleave, CUtensorMapSwizzle, CUtensorMapL2promotion,
    CUtensorMapFloatOOBfill);

extern "C" void kernel_launch(void* const* d_in, const int* in_sizes, int n_in,
                              void* d_out, int out_size) {
    const float* audio  = (const float*)d_in[0];   // (32, 512, 384) fp32
    const float* visual = (const float*)d_in[1];   // (32, 256, 384) fp32
    float* out = (float*)d_out;                    // (32, 32) fp32

    // fetch cuTensorMapEncodeTiled without linking libcuda directly
    void* fn = nullptr;
    cudaDriverEntryPointQueryResult qr;
    cudaGetDriverEntryPointByVersion("cuTensorMapEncodeTiled", &fn, 12000,
                                     cudaEnableDefault, &qr);
    PFN_encodeTM encode = (PFN_encodeTM)fn;

    void *pa = nullptr, *pv = nullptr;
    cudaGetSymbolAddress(&pa, g_audio_h);
    cudaGetSymbolAddress(&pv, g_visual_h);

    CUtensorMap mapA{}, mapV{};
    {
        cuuint64_t dims[2]    = {(cuuint64_t)D_, (cuuint64_t)(B_ * NA)};
        cuuint64_t strides[1] = {(cuuint64_t)(D_ * 2)};
        cuuint32_t box[2]     = {BKE, BM};          // 64 x 128
        cuuint32_t es[2]      = {1, 1};
        encode(&mapA, CU_TENSOR_MAP_DATA_TYPE_FLOAT16, 2, pa, dims, strides, box, es,
               CU_TENSOR_MAP_INTERLEAVE_NONE, CU_TENSOR_MAP_SWIZZLE_128B,
               CU_TENSOR_MAP_L2_PROMOTION_L2_128B, CU_TENSOR_MAP_FLOAT_OOB_FILL_NONE);
    }
    {
        cuuint64_t dims[2]    = {(cuuint64_t)D_, (cuuint64_t)(B_ * NV)};
        cuuint64_t strides[1] = {(cuuint64_t)(D_ * 2)};
        cuuint32_t box[2]     = {BKE, BN};          // 64 x 256
        cuuint32_t es[2]      = {1, 1};
        encode(&mapV, CU_TENSOR_MAP_DATA_TYPE_FLOAT16, 2, pv, dims, strides, box, es,
               CU_TENSOR_MAP_INTERLEAVE_NONE, CU_TENSOR_MAP_SWIZZLE_128B,
               CU_TENSOR_MAP_L2_PROMOTION_L2_128B, CU_TENSOR_MAP_FLOAT_OOB_FILL_NONE);
    }

    cudaFuncSetAttribute(mm_f16_lse_kernel,
                         cudaFuncAttributeMaxDynamicSharedMemorySize, SMEM_BYTES);

    cudaMemsetAsync(out, 0, (size_t)out_size * sizeof(float));
    cvt_f16_kernel<<<1184, 256>>>(audio, visual);

    dim3 grid(NA / BM, B_, B_);   // (4, 32, 32)
    mm_f16_lse_kernel<<<grid, NTHREADS, SMEM_BYTES>>>(out, mapA, mapV);
}

// round 17
// speedup vs baseline: 1.1057x; 1.0179x over previous
#include <cuda_runtime.h>
#include <cuda_fp16.h>
#include <cuda.h>
#include <cstdint>

#define B_   32
#define NA   512
#define NV   256
#define D_   384
#define BM   128
#define BN   256
#define BKE  64                     // fp16 elements per k-chunk (128 bytes/row)
#define NCH  (D_ / BKE)             // 6

#define A_TILE   (BM * 128)         // 16384 B
#define B_TILE   (BN * 128)         // 32768 B
#define STAGE_B  (A_TILE + B_TILE)  // 49152 B
#define RING_B   (2 * STAGE_B)      // 98304 B
#define SMEM_BYTES (RING_B + 64)    // + mbarriers -> 2 CTAs/SM

#define NTHREADS 256

// fp16 scratch (device globals: allocation-free)
__device__ __align__(16) __half g_audio_h[B_ * NA * D_];    // 12.6 MB
__device__ __align__(16) __half g_visual_h[B_ * NV * D_];   //  6.3 MB

// ---------------- helpers ----------------
__device__ __forceinline__ uint32_t smem_u32(const void* p) {
    uint32_t a;
    asm("{ .reg .u64 t; cvta.to.shared.u64 t, %1; cvt.u32.u64 %0, t; }" : "=r"(a) : "l"(p));
    return a;
}
#define MBAR_INIT(addr, cnt) \
    asm volatile("mbarrier.init.shared.b64 [%0], %1;" :: "r"(addr), "r"(cnt) : "memory")
#define MBAR_EXPECT(addr, bytes) \
    asm volatile("mbarrier.arrive.expect_tx.shared.b64 _, [%0], %1;" :: "r"(addr), "r"(bytes) : "memory")
#define MBAR_ARRIVE(addr) \
    asm volatile("mbarrier.arrive.shared.b64 _, [%0];" :: "r"(addr) : "memory")

__device__ __forceinline__ void mbar_wait(uint32_t mbar, uint32_t parity) {
    uint32_t done;
    asm volatile(
        "{ .reg .pred p; mbarrier.try_wait.parity.acquire.cta.shared::cta.b64 p, [%1], %2; selp.b32 %0, 1, 0, p; }"
        : "=r"(done) : "r"(mbar), "r"(parity) : "memory");
    while (!done) {
        asm volatile(
            "{ .reg .pred p; mbarrier.try_wait.parity.acquire.cta.shared::cta.b64 p, [%1], %2, 0x989680; selp.b32 %0, 1, 0, p; }"
            : "=r"(done) : "r"(mbar), "r"(parity) : "memory");
    }
}

__device__ __forceinline__ void tma2d(uint32_t dst, const CUtensorMap* map,
                                      int cx, int cy, uint32_t mbar) {
    asm volatile(
        "cp.async.bulk.tensor.2d.shared::cta.global.tile.mbarrier::complete_tx::bytes "
        "[%0], [%1, {%2, %3}], [%4];"
        :: "r"(dst), "l"(map), "r"(cx), "r"(cy), "r"(mbar) : "memory");
}

#define LDSM_X4(r, addr) \
    asm volatile("ldmatrix.sync.aligned.m8n8.x4.shared.b16 {%0,%1,%2,%3}, [%4];" \
                 : "=r"((r)[0]), "=r"((r)[1]), "=r"((r)[2]), "=r"((r)[3]) : "r"(addr))

// fp16-accumulate MMA: D,C are 2 packed-half2 regs
__device__ __forceinline__ void mma_f16(uint32_t* d, const uint32_t* a, const uint32_t* b) {
    asm volatile(
        "mma.sync.aligned.m16n8k16.row.col.f16.f16.f16.f16 "
        "{%0,%1}, {%2,%3,%4,%5}, {%6,%7}, {%0,%1};"
        : "+r"(d[0]), "+r"(d[1])
        : "r"(a[0]), "r"(a[1]), "r"(a[2]), "r"(a[3]), "r"(b[0]), "r"(b[1]));
}

__device__ __forceinline__ void lse_comb(float& m, float& s, int o) {
    float om = __shfl_xor_sync(0xffffffffu, m, o);
    float os = __shfl_xor_sync(0xffffffffu, s, o);
    float mn = fmaxf(m, om);
    s = s * __expf((m - mn) * 0.5f) + os * __expf((om - mn) * 0.5f);
    m = mn;
}

// ---------------- fp32 -> fp16 conversion ----------------
__global__ void cvt_f16_kernel(const float* __restrict__ audio,
                               const float* __restrict__ visual) {
    const int NAE = B_ * NA * D_;
    const int NVE = B_ * NV * D_;
    int stride = gridDim.x * blockDim.x;
    for (int t = blockIdx.x * blockDim.x + threadIdx.x; t < NAE / 4; t += stride) {
        float4 v = reinterpret_cast<const float4*>(audio)[t];
        __half2 p0 = __floats2half2_rn(v.x, v.y);
        __half2 p1 = __floats2half2_rn(v.z, v.w);
        reinterpret_cast<uint2*>(g_audio_h)[t] =
            make_uint2(*reinterpret_cast<uint32_t*>(&p0), *reinterpret_cast<uint32_t*>(&p1));
    }
    for (int t = blockIdx.x * blockDim.x + threadIdx.x; t < NVE / 4; t += stride) {
        float4 v = reinterpret_cast<const float4*>(visual)[t];
        __half2 p0 = __floats2half2_rn(v.x, v.y);
        __half2 p1 = __floats2half2_rn(v.z, v.w);
        reinterpret_cast<uint2*>(g_visual_h)[t] =
            make_uint2(*reinterpret_cast<uint32_t*>(&p0), *reinterpret_cast<uint32_t*>(&p1));
    }
}

// ---------------- main fused kernel ----------------
__global__ void __launch_bounds__(NTHREADS, 2)
mm_f16_lse_kernel(float* __restrict__ out,
                  const __grid_constant__ CUtensorMap mapA,
                  const __grid_constant__ CUtensorMap mapV) {
    extern __shared__ char smem[];
    const uint32_t sb = smem_u32(smem);
    const int tid   = threadIdx.x;
    const int warp  = tid >> 5;
    const int lane  = tid & 31;
    const int warpm = warp >> 2;        // 0..1 -> 64-row strip
    const int warpn = warp & 3;         // 0..3 -> 64-col quarter
    const int g     = lane >> 2;        // 0..7
    const int c     = lane & 3;         // 0..3

    const int mt_b = blockIdx.x;        // 0..3
    const int j    = blockIdx.y;        // visual batch
    const int i    = blockIdx.z;        // audio batch

    const int a_cy = i * NA + mt_b * BM;   // A row coord
    const int v_cy = j * NV;               // V row coord

    const uint32_t full0  = sb + RING_B;
    const uint32_t full1  = sb + RING_B + 8;
    const uint32_t empty0 = sb + RING_B + 16;
    const uint32_t empty1 = sb + RING_B + 24;

    uint32_t acc[4][8][2];              // packed half2: [mt][nt][row-half]
    #pragma unroll
    for (int mt = 0; mt < 4; mt++)
        #pragma unroll
        for (int nt = 0; nt < 8; nt++) { acc[mt][nt][0] = 0u; acc[mt][nt][1] = 0u; }

    if (tid == 0) {
        MBAR_INIT(full0, 1);
        MBAR_INIT(full1, 1);
        MBAR_INIT(empty0, 8);           // one arrive per warp
        MBAR_INIT(empty1, 8);
    }
    __syncthreads();

    // issue TMA pair (A box [64,128], V box [64,256]) for chunk kc into stage s
    auto tma_stage = [&](int s, int kc, uint32_t bar) {
        MBAR_EXPECT(bar, STAGE_B);
        tma2d(sb + s * STAGE_B,          &mapA, kc * BKE, a_cy, bar);
        tma2d(sb + s * STAGE_B + A_TILE, &mapV, kc * BKE, v_cy, bar);
    };

    // ---- per-lane ldmatrix address components ----
    const uint32_t a_row  = (uint32_t)(warpm * 64 + (lane & 15));
    const uint32_t a_cxtr = ((lane >> 4) & 1) * 16;
    const uint32_t b_row  = (uint32_t)(warpn * 64 + ((lane & 7) | ((lane & 16) >> 1)));
    const uint32_t b_cxtr = ((lane >> 3) & 1) * 16;
    const uint32_t swx    = (uint32_t)((lane & 7) << 4);

    // ---- compute one chunk with intra-chunk B-fragment double buffering ----
    auto compute = [&](int s) {
        const uint32_t a_base = sb + s * STAGE_B + a_row * 128;
        const uint32_t b_base = sb + s * STAGE_B + A_TILE + b_row * 128;
        uint32_t bf[2][4][4];
        {
            const uint32_t bcol0 = (uint32_t)(b_cxtr) ^ swx;
            #pragma unroll
            for (int p = 0; p < 4; p++)
                LDSM_X4(bf[0][p], b_base + p * (16 * 128) + bcol0);
        }
        #pragma unroll
        for (int ks = 0; ks < 4; ks++) {
            const uint32_t acol = (uint32_t)(ks * 32 + a_cxtr) ^ swx;
            uint32_t af[4][4];
            #pragma unroll
            for (int mt = 0; mt < 4; mt++)
                LDSM_X4(af[mt], a_base + mt * (16 * 128) + acol);
            if (ks < 3) {
                const uint32_t bcoln = (uint32_t)((ks + 1) * 32 + b_cxtr) ^ swx;
                #pragma unroll
                for (int p = 0; p < 4; p++)
                    LDSM_X4(bf[(ks + 1) & 1][p], b_base + p * (16 * 128) + bcoln);
            }
            #pragma unroll
            for (int mt = 0; mt < 4; mt++)
                #pragma unroll
                for (int p = 0; p < 4; p++) {
                    mma_f16(acc[mt][2 * p],     af[mt], &bf[ks & 1][p][0]);
                    mma_f16(acc[mt][2 * p + 1], af[mt], &bf[ks & 1][p][2]);
                }
        }
    };

    // per-warp arrive on an empty barrier (release: LDSM reads already done)
    auto warp_arrive = [&](uint32_t bar) {
        __syncwarp();
        if (lane == 0) MBAR_ARRIVE(bar);
    };

    // ---- 2-stage TMA pipeline, NO CTA-wide barriers in the mainloop ----
    if (tid == 0) {
        tma_stage(0, 0, full0);
        tma_stage(1, 1, full1);
    }

    // kc = 0 (stage 0, full parity 0)
    mbar_wait(full0, 0); compute(0); warp_arrive(empty0);
    if (tid == 0) { mbar_wait(empty0, 0); tma_stage(0, 2, full0); }
    // kc = 1 (stage 1, full parity 0)
    mbar_wait(full1, 0); compute(1); warp_arrive(empty1);
    if (tid == 0) { mbar_wait(empty1, 0); tma_stage(1, 3, full1); }
    // kc = 2 (stage 0, full parity 1)
    mbar_wait(full0, 1); compute(0); warp_arrive(empty0);
    if (tid == 0) { mbar_wait(empty0, 1); tma_stage(0, 4, full0); }
    // kc = 3 (stage 1, full parity 1)
    mbar_wait(full1, 1); compute(1); warp_arrive(empty1);
    if (tid == 0) { mbar_wait(empty1, 1); tma_stage(1, 5, full1); }
    // kc = 4 (stage 0, full parity 0) - no refill
    mbar_wait(full0, 0); compute(0);
    // kc = 5 (stage 1, full parity 0) - no refill
    mbar_wait(full1, 0); compute(1);

    // ---- one CTA barrier before smem reuse by the epilogue ----
    __syncthreads();

    // ---- epilogue: tau*logsumexp over 256 cols, mean over rows ----
    float* pmax = reinterpret_cast<float*>(smem);          // [128][4]
    float* psum = pmax + 512;                              // [128][4]
    float* wsum = pmax + 1024;                             // [4]

    #pragma unroll
    for (int mt = 0; mt < 4; mt++) {
        int r0 = warpm * 64 + mt * 16 + g;
        float v0[16], v1[16];
        #pragma unroll
        for (int nt = 0; nt < 8; nt++) {
            float2 x0 = __half22float2(*reinterpret_cast<__half2*>(&acc[mt][nt][0]));
            float2 x1 = __half22float2(*reinterpret_cast<__half2*>(&acc[mt][nt][1]));
            v0[2 * nt] = x0.x; v0[2 * nt + 1] = x0.y;
            v1[2 * nt] = x1.x; v1[2 * nt + 1] = x1.y;
        }
        float m0 = v0[0], m1 = v1[0];
        #pragma unroll
        for (int e = 1; e < 16; e++) { m0 = fmaxf(m0, v0[e]); m1 = fmaxf(m1, v1[e]); }
        float s0 = 0.f, s1 = 0.f;
        #pragma unroll
        for (int e = 0; e < 16; e++) {
            s0 += __expf((v0[e] - m0) * 0.5f);
            s1 += __expf((v1[e] - m1) * 0.5f);
        }
        lse_comb(m0, s0, 1); lse_comb(m0, s0, 2);
        lse_comb(m1, s1, 1); lse_comb(m1, s1, 2);
        if (c == 0) {
            pmax[(r0)     * 4 + warpn] = m0;  psum[(r0)     * 4 + warpn] = s0;
            pmax[(r0 + 8) * 4 + warpn] = m1;  psum[(r0 + 8) * 4 + warpn] = s1;
        }
    }
    __syncthreads();

    if (tid < 128) {
        float m = pmax[tid * 4];
        #pragma unroll
        for (int w = 1; w < 4; w++) m = fmaxf(m, pmax[tid * 4 + w]);
        float s = 0.f;
        #pragma unroll
        for (int w = 0; w < 4; w++) s += psum[tid * 4 + w] * __expf((pmax[tid * 4 + w] - m) * 0.5f);
        float lse = m + 2.0f * __logf(s);
        #pragma unroll
        for (int o = 16; o > 0; o >>= 1) lse += __shfl_xor_sync(0xffffffffu, lse, o);
        if (lane == 0) wsum[warp] = lse;
    }
    __syncthreads();
    if (tid == 0) {
        float t = wsum[0] + wsum[1] + wsum[2] + wsum[3];
        atomicAdd(&out[i * B_ + j], t * (1.0f / NA));
    }
}

// ---------------- launch ----------------
typedef CUresult (*PFN_encodeTM)(
    CUtensorMap*, CUtensorMapDataType, cuuint32_t, void*,
    const cuuint64_t*, const cuuint64_t*, const cuuint32_t*, const cuuint32_t*,
    CUtensorMapInterleave, CUtensorMapSwizzle, CUtensorMapL2promotion,
    CUtensorMapFloatOOBfill);

extern "C" void kernel_launch(void* const* d_in, const int* in_sizes, int n_in,
                              void* d_out, int out_size) {
    const float* audio  = (const float*)d_in[0];   // (32, 512, 384) fp32
    const float* visual = (const float*)d_in[1];   // (32, 256, 384) fp32
    float* out = (float*)d_out;                    // (32, 32) fp32

    // fetch cuTensorMapEncodeTiled without linking libcuda directly
    void* fn = nullptr;
    cudaDriverEntryPointQueryResult qr;
    cudaGetDriverEntryPointByVersion("cuTensorMapEncodeTiled", &fn, 12000,
                                     cudaEnableDefault, &qr);
    PFN_encodeTM encode = (PFN_encodeTM)fn;

    void *pa = nullptr, *pv = nullptr;
    cudaGetSymbolAddress(&pa, g_audio_h);
    cudaGetSymbolAddress(&pv, g_visual_h);

    CUtensorMap mapA{}, mapV{};
    {
        cuuint64_t dims[2]    = {(cuuint64_t)D_, (cuuint64_t)(B_ * NA)};
        cuuint64_t strides[1] = {(cuuint64_t)(D_ * 2)};
        cuuint32_t box[2]     = {BKE, BM};          // 64 x 128
        cuuint32_t es[2]      = {1, 1};
        encode(&mapA, CU_TENSOR_MAP_DATA_TYPE_FLOAT16, 2, pa, dims, strides, box, es,
               CU_TENSOR_MAP_INTERLEAVE_NONE, CU_TENSOR_MAP_SWIZZLE_128B,
               CU_TENSOR_MAP_L2_PROMOTION_L2_128B, CU_TENSOR_MAP_FLOAT_OOB_FILL_NONE);
    }
    {
        cuuint64_t dims[2]    = {(cuuint64_t)D_, (cuuint64_t)(B_ * NV)};
        cuuint64_t strides[1] = {(cuuint64_t)(D_ * 2)};
        cuuint32_t box[2]     = {BKE, BN};          // 64 x 256
        cuuint32_t es[2]      = {1, 1};
        encode(&mapV, CU_TENSOR_MAP_DATA_TYPE_FLOAT16, 2, pv, dims, strides, box, es,
               CU_TENSOR_MAP_INTERLEAVE_NONE, CU_TENSOR_MAP_SWIZZLE_128B,
               CU_TENSOR_MAP_L2_PROMOTION_L2_128B, CU_TENSOR_MAP_FLOAT_OOB_FILL_NONE);
    }

    cudaFuncSetAttribute(mm_f16_lse_kernel,
                         cudaFuncAttributeMaxDynamicSharedMemorySize, SMEM_BYTES);

    cudaMemsetAsync(out, 0, (size_t)out_size * sizeof(float));
    cvt_f16_kernel<<<1184, 256>>>(audio, visual);

    dim3 grid(NA / BM, B_, B_);   // (4, 32, 32)
    mm_f16_lse_kernel<<<grid, NTHREADS, SMEM_BYTES>>>(out, mapA, mapV);
}